// round 12
// baseline (speedup 1.0000x reference)
#include <cuda_runtime.h>

#define HH 128
#define WW 128
#define NIMG 2
#define NC 21
#define PL (HH * WW)
#define NBLK (4 * HH * NIMG)   // 1024 blocks: (xquarter, y, n)

// exp(-0.5 v) = exp2(v * -0.72134752)
#define NEG_HALF_LOG2E (-0.72134752f)

__device__ double   g_accs[32];   // spread accumulators (zero-init; self-reset)
__device__ unsigned g_cnt;

typedef unsigned long long u64;

// ---- packed f32x2 helpers (FFMA2 path; ptxas never emits these from C++) ----
__device__ __forceinline__ u64 pk(float lo, float hi) {
    u64 r;
    asm("mov.b64 %0, {%1, %2};" : "=l"(r) : "f"(lo), "f"(hi));
    return r;
}
__device__ __forceinline__ void fma2(u64& d, u64 a, u64 b) {
    asm("fma.rn.f32x2 %0, %1, %2, %0;" : "+l"(d) : "l"(a), "l"(b));
}
__device__ __forceinline__ float2 unpk(u64 v) {
    float lo, hi;
    asm("mov.b64 {%0, %1}, %2;" : "=f"(lo), "=f"(hi) : "l"(v));
    return make_float2(lo, hi);
}
// 16B shared load -> two packed f32x2 operands, zero pack MOVs
__device__ __forceinline__ void lds_v2u64(u64& a, u64& b, const float* p) {
    unsigned saddr = (unsigned)__cvta_generic_to_shared(p);
    asm("ld.shared.v2.b64 {%0, %1}, [%2];" : "=l"(a), "=l"(b) : "r"(saddr));
}

// exp(-k^2/72) for k = 0..5 (compile-time folded)
__device__ __forceinline__ constexpr float exy_tab(int k) {
    constexpr float E[6] = {1.0f, 0.98620712f, 0.94595947f,
                            0.88249690f, 0.80073740f, 0.70664828f};
    return E[k];
}

// ---------------------------------------------------------------------------
// Phase-2 worker: warp-group G handles slots with slot%4 == G.
// pool is rgb-interleaved float4 -> ONE LDS.128 per tap (was 3 scalar LDS).
// Non-forward / OOB slots written EXACTLY 0 (phase 3 relies on it).
// ---------------------------------------------------------------------------
template <int G>
__device__ __forceinline__ float phase2_slots(const float4 (*pool)[48],
                                              float (*K2s)[32],
                                              int px, int x, int y,
                                              float r0, float g0, float b0) {
    const int c0 = px + 8;
    float t1 = 0.0f;
#pragma unroll
    for (int r = 0; r <= 5; r++) {
#pragma unroll
        for (int dxi = 0; dxi < 11; dxi++) {
            const int slot = r * 11 + dxi;
            if ((slot & 3) == G) {
                const int dx = dxi - 5;
                const bool fwd = (r > 0) || (dx > 0);
                float k2 = 0.0f;
                if (fwd && (y + r < HH) && ((unsigned)(x + dx) < (unsigned)WW)) {
                    const float exy = exy_tab(r) * exy_tab(dx < 0 ? -dx : dx);
                    float4 v = pool[r][c0 + dx];       // LDS.128
                    float dr = v.x - r0;
                    float dg = v.y - g0;
                    float db = v.z - b0;
                    float q  = fmaf(dr, dr, fmaf(dg, dg, db * db));
                    float e  = exp2f(q * NEG_HALF_LOG2E);
                    k2 = fmaf(1.8f * exy, e, 0.2f * exy);
                }
                t1 += k2;
                K2s[slot][px] = k2;
            }
        }
    }
    return t1;
}

// ---------------------------------------------------------------------------
// ONE fused kernel. Block = quarter-row (32 px), 128 threads, 7 blocks/SM
// (single wave: 1036 >= 1024). Phase 3 packed f32x2, clamped loads,
// center-float4 cached across the two d-halves.
// ---------------------------------------------------------------------------
__global__ void __launch_bounds__(128, 7) crf_fused(const float* __restrict__ Y,
                                                    const float* __restrict__ rgb,
                                                    float* __restrict__ out) {
    const int xq = blockIdx.x;           // 0..3
    const int y  = blockIdx.y;           // 0..127
    const int n  = blockIdx.z;           // 0..1
    const int x0base = xq * 32;
    const int tid = threadIdx.x;

    __shared__ float4 pool[6][48];                       // rgb-interleaved + halo
    __shared__ __align__(16) float K2s[66][32];          // slot = r*11 + (dx+5)
    __shared__ float red[4];

    // ---- hoisted: center-Y loads (latency overlapped with phases 1-2) ----
    const int q_  = tid & 7;
    const int cg_ = (tid >> 3) % 7;
    const int x0_ = x0base + 4 * q_;
    const float* ybase_ = Y + (size_t)n * NC * PL + (size_t)cg_ * 3 * PL;
    u64 yp01[3], yp23[3];
#pragma unroll
    for (int c = 0; c < 3; c++) {
        float4 v = __ldg((const float4*)(ybase_ + (size_t)c * PL + y * WW + x0_));
        yp01[c] = pk(v.x, v.y);
        yp23[c] = pk(v.z, v.w);
    }

    // ---------------- Phase 1: 2x2 mean pool (x10), rgb-interleaved ----------
    {
        const float* rbase = rgb + (size_t)n * 3 * 256 * 256;
#pragma unroll
        for (int it = 0; it < 7; it++) {
            int idx = it * 128 + tid;
            if (idx < 6 * 3 * 48) {
                int ci = idx % 48;
                int ch = (idx / 48) % 3;
                int rr = idx / 144;
                int cc = min(max(x0base - 8 + ci, 0), 127);   // clamp; garbage-safe
                int ry = min(y + rr, 127);
                const float* p = rbase + (size_t)ch * (256 * 256) + (2 * ry) * 256 + 2 * cc;
                float2 a = __ldg((const float2*)p);
                float2 b = __ldg((const float2*)(p + 256));
                ((float*)&pool[rr][ci])[ch] = (a.x + a.y + b.x + b.y) * 2.5f;
            }
        }
    }
    __syncthreads();

    // ---------------- Phase 2: K2 + term1 ----------------
    float t1;
    {
        const int px = tid & 31;
        const int g  = tid >> 5;          // warp-uniform
        const int x  = x0base + px;
        float4 ctr = pool[0][px + 8];
        const float r0 = ctr.x, g0 = ctr.y, b0 = ctr.z;

        if      (g == 0) t1 = phase2_slots<0>(pool, K2s, px, x, y, r0, g0, b0);
        else if (g == 1) t1 = phase2_slots<1>(pool, K2s, px, x, y, r0, g0, b0);
        else if (g == 2) t1 = phase2_slots<2>(pool, K2s, px, x, y, r0, g0, b0);
        else             t1 = phase2_slots<3>(pool, K2s, px, x, y, r0, g0, b0);

        if (g == 0) {  // OOB (zero-padded feature) taps, closed form, once per px
            int xl = max(x - 5, 0), xr = min(x + 5, WW - 1);
            int yl = max(y - 5, 0), yr = min(y + 5, HH - 1);
            float oob = 121.0f - (float)((xr - xl + 1) * (yr - yl + 1));
            float ep  = exp2f((float)(x * x + y * y) * (NEG_HALF_LOG2E / 36.0f));
            float ec  = exp2f(fmaf(r0, r0, fmaf(g0, g0, b0 * b0)) * NEG_HALF_LOG2E);
            t1 += oob * ep * (0.9f * ec + 0.1f);
        }
    }
    __syncthreads();

    // ---------------- Phase 3: term2 (packed f32x2 s-matrix) ----------------
    float t2 = 0.0f;
    if (tid < 112) {                      // 2 rowgroups x 7 cgroups x 8 quads
        const int q  = q_;
        const int x0 = x0_;
        const int rg = tid / 56;          // rows rg*3 .. rg*3+2
        const float* ybase = ybase_;

        // clamped, float4-aligned column offsets — garbage lands on K2==0 taps
        const int om8 = max(x0 - 8, 0);
        const int om4 = max(x0 - 4, 0);
        const int op4 = min(x0 + 4, WW - 4);
        const int op8 = min(x0 + 8, WW - 4);

        u64 acc01 = 0ull, acc23 = 0ull;   // packed (+0,+0)

#pragma unroll
        for (int rr = 0; rr < 3; rr++) {
            int r = rg * 3 + rr;
            if (y + r < HH) {
                const float* krow = &K2s[r * 11][0] + 4 * q;
                const float* rowb = ybase + (size_t)(y + r) * WW;

                float4 cC[3];             // center cache, reused in half B

                // ===== half A: d = 0..4 =====
                {
                    u64 sA[5][2];
#pragma unroll
                    for (int d = 0; d < 5; d++) { sA[d][0] = 0ull; sA[d][1] = 0ull; }

#pragma unroll
                    for (int c = 0; c < 3; c++) {
                        const float* rc = rowb + (size_t)c * PL;
                        float w[12];
                        float4 v;
                        v = __ldg((const float4*)(rc + om8));
                        w[0] = v.x; w[1] = v.y; w[2] = v.z; w[3] = v.w;
                        v = __ldg((const float4*)(rc + om4));
                        w[4] = v.x; w[5] = v.y; w[6] = v.z; w[7] = v.w;
                        v = __ldg((const float4*)(rc + x0));
                        cC[c] = v;
                        w[8] = v.x; w[9] = v.y; w[10] = v.z; w[11] = v.w;

                        u64 P[10];
#pragma unroll
                        for (int a = 3; a <= 9; a++) P[a] = pk(w[a], w[a + 1]);

#pragma unroll
                        for (int d = 0; d < 5; d++) {
                            fma2(sA[d][0], yp01[c], P[3 + d]);
                            fma2(sA[d][1], yp23[c], P[5 + d]);
                        }
                    }
#pragma unroll
                    for (int d = 0; d < 5; d++) {
                        u64 k01, k23;
                        lds_v2u64(k01, k23, krow + d * 32);
                        fma2(acc01, k01, sA[d][0]);
                        fma2(acc23, k23, sA[d][1]);
                    }
                }

                // ===== half B: d = 5..10, center from cache =====
                {
                    u64 sB[6][2];
#pragma unroll
                    for (int d = 0; d < 6; d++) { sB[d][0] = 0ull; sB[d][1] = 0ull; }

#pragma unroll
                    for (int c = 0; c < 3; c++) {
                        const float* rc = rowb + (size_t)c * PL;
                        float w[12];
                        float4 v = cC[c];
                        w[0] = v.x; w[1] = v.y; w[2] = v.z; w[3] = v.w;
                        v = __ldg((const float4*)(rc + op4));
                        w[4] = v.x; w[5] = v.y; w[6] = v.z; w[7] = v.w;
                        v = __ldg((const float4*)(rc + op8));
                        w[8] = v.x; w[9] = v.y; w[10] = v.z; w[11] = v.w;

                        u64 P[8];
#pragma unroll
                        for (int a = 0; a <= 7; a++) P[a] = pk(w[a], w[a + 1]);

#pragma unroll
                        for (int d = 5; d < 11; d++) {
                            fma2(sB[d - 5][0], yp01[c], P[d - 5]);
                            fma2(sB[d - 5][1], yp23[c], P[d - 3]);
                        }
                    }
#pragma unroll
                    for (int d = 5; d < 11; d++) {
                        u64 k01, k23;
                        lds_v2u64(k01, k23, krow + d * 32);
                        fma2(acc01, k01, sB[d - 5][0]);
                        fma2(acc23, k23, sB[d - 5][1]);
                    }
                }
            }
        }
        float2 a01 = unpk(acc01);
        float2 a23 = unpk(acc23);
        t2 = (a01.x + a01.y) + (a23.x + a23.y);
    }

    // ---------------- Epilogue: reduce + finalize ----------------
    float v = t1 - t2;
#pragma unroll
    for (int sft = 16; sft > 0; sft >>= 1)
        v += __shfl_down_sync(0xFFFFFFFFu, v, sft);

    int lane = tid & 31, warp = tid >> 5;
    if (lane == 0) red[warp] = v;
    __syncthreads();
    if (tid == 0) {
        float bs = (red[0] + red[1]) + (red[2] + red[3]);
        int slot = ((blockIdx.y & 7) << 2) | blockIdx.x;   // 32 spread slots
        atomicAdd(&g_accs[slot], (double)bs);
        __threadfence();
        unsigned old = atomicAdd(&g_cnt, 1u);
        if (old == (unsigned)(NBLK - 1)) {
            double tot = 0.0;
#pragma unroll
            for (int i = 0; i < 32; i++) {
                tot += atomicAdd(&g_accs[i], 0.0);
                g_accs[i] = 0.0;                 // self-reset for graph replay
            }
            out[0] = (float)(tot / (double)(NIMG * HH * WW));
            g_cnt = 0u;
        }
    }
}

extern "C" void kernel_launch(void* const* d_in, const int* in_sizes, int n_in,
                              void* d_out, int out_size) {
    const float* y   = (const float*)d_in[0];
    const float* rgb = (const float*)d_in[1];
    if (n_in >= 2 && in_sizes[0] == NIMG * 3 * 256 * 256) {
        const float* t = y; y = rgb; rgb = t;
    }

    dim3 grid(4, HH, NIMG);   // 1024 blocks, single wave at 7 blocks/SM
    crf_fused<<<grid, 128>>>(y, rgb, (float*)d_out);
}

// round 13
// speedup vs baseline: 1.0152x; 1.0152x over previous
#include <cuda_runtime.h>

#define HH 128
#define WW 128
#define NIMG 2
#define NC 21
#define PL (HH * WW)
#define NBLK (4 * HH * NIMG)   // 1024 blocks: (xquarter, y, n)

// pool scale: 0.25 (2x2 mean) * 10 (1/sigma_rgb) * sqrt(0.5*ln2e...) —
// precisely 2.5 * sqrt(0.72134752) so that t = -(dr^2+dg^2+db^2) is the
// exp2 exponent directly: exp(-0.5 * |d(10*rgb)|^2) = 2^t.
#define POOL_SCALE 2.1233048f
#define NEG_HALF_LOG2E (-0.72134752f)

__device__ double   g_accs[32];   // spread accumulators (zero-init; self-reset)
__device__ unsigned g_cnt;

typedef unsigned long long u64;

// ---- packed f32x2 helpers (FFMA2 path) ----
__device__ __forceinline__ u64 pk(float lo, float hi) {
    u64 r;
    asm("mov.b64 %0, {%1, %2};" : "=l"(r) : "f"(lo), "f"(hi));
    return r;
}
__device__ __forceinline__ void fma2(u64& d, u64 a, u64 b) {
    asm("fma.rn.f32x2 %0, %1, %2, %0;" : "+l"(d) : "l"(a), "l"(b));
}
__device__ __forceinline__ float2 unpk(u64 v) {
    float lo, hi;
    asm("mov.b64 {%0, %1}, %2;" : "=f"(lo), "=f"(hi) : "l"(v));
    return make_float2(lo, hi);
}
__device__ __forceinline__ void lds_v2u64(u64& a, u64& b, const float* p) {
    unsigned saddr = (unsigned)__cvta_generic_to_shared(p);
    asm("ld.shared.v2.b64 {%0, %1}, [%2];" : "=l"(a), "=l"(b) : "r"(saddr));
}

// MUFU exp2 (1 op on the XU pipe)
__device__ __forceinline__ float ex2_mufu(float t) {
    float e;
    asm("ex2.approx.f32 %0, %1;" : "=f"(e) : "f"(t));
    return e;
}

// FFMA-pipe exp2 for t <= 0: magic round + cubic 2^r on [-0.5,0.5].
// Max rel error ~1e-4. Runs entirely on fma/alu pipes -> offloads MUFU.
__device__ __forceinline__ float ex2_poly(float t) {
    float tc = fmaxf(t, -126.0f);
    float z  = __fadd_rn(tc, 12582912.0f);       // 1.5*2^23: RN -> round(tc)
    float fi = __fadd_rn(z, -12582912.0f);       // = round(tc) exactly
    float r  = __fadd_rn(tc, -fi);               // in [-0.5, 0.5]
    unsigned zi = (unsigned)__float_as_int(z);
    float s = __int_as_float((int)((zi << 23) + 0x3F800000u));  // 2^round(tc)
    float p = fmaf(r, fmaf(r, fmaf(r, 0.0554983f, 0.2426311f),
                           0.6931472f), 0.99992487f);
    return s * p;
}

// exp(-k^2/72) for k = 0..5 (compile-time folded)
__device__ __forceinline__ constexpr float exy_tab(int k) {
    constexpr float E[6] = {1.0f, 0.98620712f, 0.94595947f,
                            0.88249690f, 0.80073740f, 0.70664828f};
    return E[k];
}

// ---------------------------------------------------------------------------
// Phase-2 worker: warp-group G handles slots with slot%4 == G.
// pool rgb-interleaved float4 (prescaled by POOL_SCALE).
// ~29% of slots use the FFMA-pipe exp2; the rest use MUFU — balances the
// MUFU pipe (the measured bottleneck: 3.4K exps/SMSP x 8cyc = full duration).
// Non-forward / OOB slots written EXACTLY 0.
// ---------------------------------------------------------------------------
template <int G>
__device__ __forceinline__ float phase2_slots(const float4 (*pool)[48],
                                              float (*K2s)[32],
                                              int px, int x, int y,
                                              float r0, float g0, float b0) {
    const int c0 = px + 8;
    float t1 = 0.0f;
#pragma unroll
    for (int r = 0; r <= 5; r++) {
#pragma unroll
        for (int dxi = 0; dxi < 11; dxi++) {
            const int slot = r * 11 + dxi;
            if ((slot & 3) == G) {
                const int dx = dxi - 5;
                const bool fwd = (r > 0) || (dx > 0);
                const bool use_poly = ((slot >> 2) < 5);   // ~29% of slots
                float k2 = 0.0f;
                if (fwd && (y + r < HH) && ((unsigned)(x + dx) < (unsigned)WW)) {
                    const float exy = exy_tab(r) * exy_tab(dx < 0 ? -dx : dx);
                    float4 v = pool[r][c0 + dx];       // LDS.128
                    float dr = v.x - r0;
                    float dg = v.y - g0;
                    float db = v.z - b0;
                    float t  = -dr * dr;
                    t = fmaf(dg, -dg, t);
                    t = fmaf(db, -db, t);              // t = exp2 exponent (<=0)
                    float e = use_poly ? ex2_poly(t) : ex2_mufu(t);
                    k2 = fmaf(1.8f * exy, e, 0.2f * exy);
                }
                t1 += k2;
                K2s[slot][px] = k2;
            }
        }
    }
    return t1;
}

// ---------------------------------------------------------------------------
// ONE fused kernel. Block = quarter-row (32 px), 128 threads, 7 blocks/SM
// (single wave: 1036 >= 1024).
// ---------------------------------------------------------------------------
__global__ void __launch_bounds__(128, 7) crf_fused(const float* __restrict__ Y,
                                                    const float* __restrict__ rgb,
                                                    float* __restrict__ out) {
    const int xq = blockIdx.x;           // 0..3
    const int y  = blockIdx.y;           // 0..127
    const int n  = blockIdx.z;           // 0..1
    const int x0base = xq * 32;
    const int tid = threadIdx.x;

    __shared__ float4 pool[6][48];                       // rgb-interleaved + halo
    __shared__ __align__(16) float K2s[66][32];          // slot = r*11 + (dx+5)
    __shared__ float red[4];

    // ---- hoisted: center-Y loads (latency overlapped with phases 1-2) ----
    const int q_  = tid & 7;
    const int cg_ = (tid >> 3) % 7;
    const int x0_ = x0base + 4 * q_;
    const float* ybase_ = Y + (size_t)n * NC * PL + (size_t)cg_ * 3 * PL;
    u64 yp01[3], yp23[3];
#pragma unroll
    for (int c = 0; c < 3; c++) {
        float4 v = __ldg((const float4*)(ybase_ + (size_t)c * PL + y * WW + x0_));
        yp01[c] = pk(v.x, v.y);
        yp23[c] = pk(v.z, v.w);
    }

    // ---------------- Phase 1: 2x2 mean pool (prescaled), rgb-interleaved ----
    {
        const float* rbase = rgb + (size_t)n * 3 * 256 * 256;
#pragma unroll
        for (int it = 0; it < 7; it++) {
            int idx = it * 128 + tid;
            if (idx < 6 * 3 * 48) {
                int ci = idx % 48;
                int ch = (idx / 48) % 3;
                int rr = idx / 144;
                int cc = min(max(x0base - 8 + ci, 0), 127);   // clamp; garbage-safe
                int ry = min(y + rr, 127);
                const float* p = rbase + (size_t)ch * (256 * 256) + (2 * ry) * 256 + 2 * cc;
                float2 a = __ldg((const float2*)p);
                float2 b = __ldg((const float2*)(p + 256));
                ((float*)&pool[rr][ci])[ch] = (a.x + a.y + b.x + b.y) * POOL_SCALE;
            }
        }
    }
    __syncthreads();

    // ---------------- Phase 2: K2 + term1 ----------------
    float t1;
    {
        const int px = tid & 31;
        const int g  = tid >> 5;          // warp-uniform
        const int x  = x0base + px;
        float4 ctr = pool[0][px + 8];
        const float r0 = ctr.x, g0 = ctr.y, b0 = ctr.z;

        if      (g == 0) t1 = phase2_slots<0>(pool, K2s, px, x, y, r0, g0, b0);
        else if (g == 1) t1 = phase2_slots<1>(pool, K2s, px, x, y, r0, g0, b0);
        else if (g == 2) t1 = phase2_slots<2>(pool, K2s, px, x, y, r0, g0, b0);
        else             t1 = phase2_slots<3>(pool, K2s, px, x, y, r0, g0, b0);

        if (g == 0) {  // OOB (zero-padded feature) taps, closed form, once per px
            int xl = max(x - 5, 0), xr = min(x + 5, WW - 1);
            int yl = max(y - 5, 0), yr = min(y + 5, HH - 1);
            float oob = 121.0f - (float)((xr - xl + 1) * (yr - yl + 1));
            float ep  = ex2_mufu((float)(x * x + y * y) * (NEG_HALF_LOG2E / 36.0f));
            float tc  = -r0 * r0;
            tc = fmaf(g0, -g0, tc);
            tc = fmaf(b0, -b0, tc);
            float ec  = ex2_mufu(tc);     // pool prescale makes this exact
            t1 += oob * ep * (0.9f * ec + 0.1f);
        }
    }
    __syncthreads();

    // ---------------- Phase 3: term2 (packed f32x2 s-matrix) ----------------
    float t2 = 0.0f;
    if (tid < 112) {                      // 2 rowgroups x 7 cgroups x 8 quads
        const int q  = q_;
        const int x0 = x0_;
        const int rg = tid / 56;          // rows rg*3 .. rg*3+2
        const float* ybase = ybase_;

        // clamped, float4-aligned column offsets — garbage lands on K2==0 taps
        const int om8 = max(x0 - 8, 0);
        const int om4 = max(x0 - 4, 0);
        const int op4 = min(x0 + 4, WW - 4);
        const int op8 = min(x0 + 8, WW - 4);

        u64 acc01 = 0ull, acc23 = 0ull;   // packed (+0,+0)

#pragma unroll
        for (int rr = 0; rr < 3; rr++) {
            int r = rg * 3 + rr;
            if (y + r < HH) {
                const float* krow = &K2s[r * 11][0] + 4 * q;
                const float* rowb = ybase + (size_t)(y + r) * WW;

                float4 cC[3];             // center cache, reused in half B

                // ===== half A: d = 0..4 =====
                {
                    u64 sA[5][2];
#pragma unroll
                    for (int d = 0; d < 5; d++) { sA[d][0] = 0ull; sA[d][1] = 0ull; }

#pragma unroll
                    for (int c = 0; c < 3; c++) {
                        const float* rc = rowb + (size_t)c * PL;
                        float w[12];
                        float4 v;
                        v = __ldg((const float4*)(rc + om8));
                        w[0] = v.x; w[1] = v.y; w[2] = v.z; w[3] = v.w;
                        v = __ldg((const float4*)(rc + om4));
                        w[4] = v.x; w[5] = v.y; w[6] = v.z; w[7] = v.w;
                        v = __ldg((const float4*)(rc + x0));
                        cC[c] = v;
                        w[8] = v.x; w[9] = v.y; w[10] = v.z; w[11] = v.w;

                        u64 P[10];
#pragma unroll
                        for (int a = 3; a <= 9; a++) P[a] = pk(w[a], w[a + 1]);

#pragma unroll
                        for (int d = 0; d < 5; d++) {
                            fma2(sA[d][0], yp01[c], P[3 + d]);
                            fma2(sA[d][1], yp23[c], P[5 + d]);
                        }
                    }
#pragma unroll
                    for (int d = 0; d < 5; d++) {
                        u64 k01, k23;
                        lds_v2u64(k01, k23, krow + d * 32);
                        fma2(acc01, k01, sA[d][0]);
                        fma2(acc23, k23, sA[d][1]);
                    }
                }

                // ===== half B: d = 5..10, center from cache =====
                {
                    u64 sB[6][2];
#pragma unroll
                    for (int d = 0; d < 6; d++) { sB[d][0] = 0ull; sB[d][1] = 0ull; }

#pragma unroll
                    for (int c = 0; c < 3; c++) {
                        const float* rc = rowb + (size_t)c * PL;
                        float w[12];
                        float4 v = cC[c];
                        w[0] = v.x; w[1] = v.y; w[2] = v.z; w[3] = v.w;
                        v = __ldg((const float4*)(rc + op4));
                        w[4] = v.x; w[5] = v.y; w[6] = v.z; w[7] = v.w;
                        v = __ldg((const float4*)(rc + op8));
                        w[8] = v.x; w[9] = v.y; w[10] = v.z; w[11] = v.w;

                        u64 P[8];
#pragma unroll
                        for (int a = 0; a <= 7; a++) P[a] = pk(w[a], w[a + 1]);

#pragma unroll
                        for (int d = 5; d < 11; d++) {
                            fma2(sB[d - 5][0], yp01[c], P[d - 5]);
                            fma2(sB[d - 5][1], yp23[c], P[d - 3]);
                        }
                    }
#pragma unroll
                    for (int d = 5; d < 11; d++) {
                        u64 k01, k23;
                        lds_v2u64(k01, k23, krow + d * 32);
                        fma2(acc01, k01, sB[d - 5][0]);
                        fma2(acc23, k23, sB[d - 5][1]);
                    }
                }
            }
        }
        float2 a01 = unpk(acc01);
        float2 a23 = unpk(acc23);
        t2 = (a01.x + a01.y) + (a23.x + a23.y);
    }

    // ---------------- Epilogue: reduce + finalize ----------------
    float v = t1 - t2;
#pragma unroll
    for (int sft = 16; sft > 0; sft >>= 1)
        v += __shfl_down_sync(0xFFFFFFFFu, v, sft);

    int lane = tid & 31, warp = tid >> 5;
    if (lane == 0) red[warp] = v;
    __syncthreads();
    if (tid == 0) {
        float bs = (red[0] + red[1]) + (red[2] + red[3]);
        int slot = ((blockIdx.y & 7) << 2) | blockIdx.x;   // 32 spread slots
        atomicAdd(&g_accs[slot], (double)bs);
        __threadfence();
        unsigned old = atomicAdd(&g_cnt, 1u);
        if (old == (unsigned)(NBLK - 1)) {
            double tot = 0.0;
#pragma unroll
            for (int i = 0; i < 32; i++) {
                tot += atomicAdd(&g_accs[i], 0.0);
                g_accs[i] = 0.0;                 // self-reset for graph replay
            }
            out[0] = (float)(tot / (double)(NIMG * HH * WW));
            g_cnt = 0u;
        }
    }
}

extern "C" void kernel_launch(void* const* d_in, const int* in_sizes, int n_in,
                              void* d_out, int out_size) {
    const float* y   = (const float*)d_in[0];
    const float* rgb = (const float*)d_in[1];
    if (n_in >= 2 && in_sizes[0] == NIMG * 3 * 256 * 256) {
        const float* t = y; y = rgb; rgb = t;
    }

    dim3 grid(4, HH, NIMG);   // 1024 blocks, single wave at 7 blocks/SM
    crf_fused<<<grid, 128>>>(y, rgb, (float*)d_out);
}

// round 14
// speedup vs baseline: 1.0308x; 1.0154x over previous
#include <cuda_runtime.h>

#define HH 128
#define WW 128
#define NIMG 2
#define NC 21
#define PL (HH * WW)
#define NBLK (4 * HH * NIMG)   // 1024 blocks: (xquarter, y, n)

// pool scale: 0.25 (2x2 mean) * 10 (1/sigma_rgb) * sqrt(0.72134752) so that
// t = -(dr^2+dg^2+db^2) is directly the exp2 exponent.
#define POOL_SCALE 2.1233048f
#define NEG_HALF_LOG2E (-0.72134752f)

__device__ double   g_accs[32];   // spread accumulators (zero-init; self-reset)
__device__ unsigned g_cnt;

typedef unsigned long long u64;

// ---- packed f32x2 helpers (FFMA2 path) ----
__device__ __forceinline__ u64 pk(float lo, float hi) {
    u64 r;
    asm("mov.b64 %0, {%1, %2};" : "=l"(r) : "f"(lo), "f"(hi));
    return r;
}
__device__ __forceinline__ void fma2(u64& d, u64 a, u64 b) {
    asm("fma.rn.f32x2 %0, %1, %2, %0;" : "+l"(d) : "l"(a), "l"(b));
}
__device__ __forceinline__ float2 unpk(u64 v) {
    float lo, hi;
    asm("mov.b64 {%0, %1}, %2;" : "=f"(lo), "=f"(hi) : "l"(v));
    return make_float2(lo, hi);
}
__device__ __forceinline__ void lds_v2u64(u64& a, u64& b, const float* p) {
    unsigned saddr = (unsigned)__cvta_generic_to_shared(p);
    asm("ld.shared.v2.b64 {%0, %1}, [%2];" : "=l"(a), "=l"(b) : "r"(saddr));
}
__device__ __forceinline__ float ex2_mufu(float t) {
    float e;
    asm("ex2.approx.f32 %0, %1;" : "=f"(e) : "f"(t));
    return e;
}

// exp(-k^2/72) for k = 0..5 (compile-time folded)
__device__ __forceinline__ constexpr float exy_tab(int k) {
    constexpr float E[6] = {1.0f, 0.98620712f, 0.94595947f,
                            0.88249690f, 0.80073740f, 0.70664828f};
    return E[k];
}

// ---------------------------------------------------------------------------
// Phase-2 worker: warp-group G handles slots with slot%4 == G. BRANCHLESS:
// every tap always loads + exps; a single SEL zeroes OOB taps. Non-forward /
// OOB slots end up EXACTLY 0 in K2s (phase 3 relies on this).
// ---------------------------------------------------------------------------
template <int G>
__device__ __forceinline__ float phase2_slots(const float4 (*pool)[48],
                                              float (*K2s)[32],
                                              int px, int x, int y,
                                              float r0, float g0, float b0) {
    const int c0 = px + 8;
    float t1 = 0.0f;
#pragma unroll
    for (int r = 0; r <= 5; r++) {
#pragma unroll
        for (int dxi = 0; dxi < 11; dxi++) {
            const int slot = r * 11 + dxi;
            if ((slot & 3) == G) {
                const int dx = dxi - 5;
                const bool fwd = (r > 0) || (dx > 0);   // compile-time
                if (fwd) {
                    // always compute; SEL kills OOB
                    const float exy = exy_tab(r) * exy_tab(dx < 0 ? -dx : dx);
                    float4 v = pool[r][c0 + dx];        // LDS.128 (clamped fill)
                    float dr = v.x - r0;
                    float dg = v.y - g0;
                    float db = v.z - b0;
                    float t  = -dr * dr;
                    t = fmaf(dg, -dg, t);
                    t = fmaf(db, -db, t);
                    float e  = ex2_mufu(t);
                    float kv = fmaf(1.8f * exy, e, 0.2f * exy);
                    bool ok  = (y + r < HH) && ((unsigned)(x + dx) < (unsigned)WW);
                    float k2 = ok ? kv : 0.0f;          // SEL, no branch
                    t1 += k2;
                    K2s[slot][px] = k2;
                } else {
                    K2s[slot][px] = 0.0f;
                }
            }
        }
    }
    return t1;
}

// ---------------------------------------------------------------------------
// ONE fused kernel. Block = quarter-row (32 px), 128 threads, 7 blocks/SM
// (single wave: 1036 >= 1024). Phase 3 is STRAIGHT-LINE: row indices clamped,
// OOB rows annihilated by K2==0 -> ptxas can batch all window LDGs.
// ---------------------------------------------------------------------------
__global__ void __launch_bounds__(128, 7) crf_fused(const float* __restrict__ Y,
                                                    const float* __restrict__ rgb,
                                                    float* __restrict__ out) {
    const int xq = blockIdx.x;           // 0..3
    const int y  = blockIdx.y;           // 0..127
    const int n  = blockIdx.z;           // 0..1
    const int x0base = xq * 32;
    const int tid = threadIdx.x;

    __shared__ float4 pool[6][48];                       // rgb-interleaved + halo
    __shared__ __align__(16) float K2s[66][32];          // slot = r*11 + (dx+5)
    __shared__ float red[4];

    // ---- hoisted: center-Y loads (latency overlapped with phases 1-2) ----
    const int q_  = tid & 7;
    const int cg_ = (tid >> 3) % 7;
    const int x0_ = x0base + 4 * q_;
    const float* ybase_ = Y + (size_t)n * NC * PL + (size_t)cg_ * 3 * PL;
    u64 yp01[3], yp23[3];
#pragma unroll
    for (int c = 0; c < 3; c++) {
        float4 v = __ldg((const float4*)(ybase_ + (size_t)c * PL + y * WW + x0_));
        yp01[c] = pk(v.x, v.y);
        yp23[c] = pk(v.z, v.w);
    }

    // ---------------- Phase 1: 2x2 mean pool, float4 2-output items ----------
    {
        const float* rbase = rgb + (size_t)n * 3 * 256 * 256;
#pragma unroll
        for (int it = 0; it < 4; it++) {
            int idx = it * 128 + tid;                 // 432 pair-items
            if (idx < 6 * 3 * 24) {
                int cp = (idx % 24) * 2;              // even output col within 48
                int ch = (idx / 24) % 3;
                int rr = idx / 72;
                int cg = x0base - 8 + cp;             // even by construction
                int cc = min(max(cg, 0), 126);        // even clamp; garbage-safe
                int ry = min(y + rr, 127);
                const float* p = rbase + (size_t)ch * (256 * 256) + (2 * ry) * 256 + 2 * cc;
                float4 a = __ldg((const float4*)p);
                float4 b = __ldg((const float4*)(p + 256));
                ((float*)&pool[rr][cp])[ch]     = (a.x + a.y + b.x + b.y) * POOL_SCALE;
                ((float*)&pool[rr][cp + 1])[ch] = (a.z + a.w + b.z + b.w) * POOL_SCALE;
            }
        }
    }
    __syncthreads();

    // ---------------- Phase 2: K2 + term1 (branchless taps) ----------------
    float t1;
    {
        const int px = tid & 31;
        const int g  = tid >> 5;          // warp-uniform
        const int x  = x0base + px;
        float4 ctr = pool[0][px + 8];
        const float r0 = ctr.x, g0 = ctr.y, b0 = ctr.z;

        if      (g == 0) t1 = phase2_slots<0>(pool, K2s, px, x, y, r0, g0, b0);
        else if (g == 1) t1 = phase2_slots<1>(pool, K2s, px, x, y, r0, g0, b0);
        else if (g == 2) t1 = phase2_slots<2>(pool, K2s, px, x, y, r0, g0, b0);
        else             t1 = phase2_slots<3>(pool, K2s, px, x, y, r0, g0, b0);

        if (g == 0) {  // OOB (zero-padded feature) taps, closed form, once per px
            int xl = max(x - 5, 0), xr = min(x + 5, WW - 1);
            int yl = max(y - 5, 0), yr = min(y + 5, HH - 1);
            float oob = 121.0f - (float)((xr - xl + 1) * (yr - yl + 1));
            float ep  = ex2_mufu((float)(x * x + y * y) * (NEG_HALF_LOG2E / 36.0f));
            float tc  = -r0 * r0;
            tc = fmaf(g0, -g0, tc);
            tc = fmaf(b0, -b0, tc);
            float ec  = ex2_mufu(tc);     // pool prescale makes this exact
            t1 += oob * ep * (0.9f * ec + 0.1f);
        }
    }
    __syncthreads();

    // ---------------- Phase 3: term2 — STRAIGHT-LINE s-matrix ----------------
    float t2 = 0.0f;
    if (tid < 112) {                      // 2 rowgroups x 7 cgroups x 8 quads
        const int q  = q_;
        const int x0 = x0_;
        const int rg = tid / 56;          // rows rg*3 .. rg*3+2
        const float* ybase = ybase_;

        // clamped, float4-aligned column offsets — garbage lands on K2==0 taps
        const int om8 = max(x0 - 8, 0);
        const int om4 = max(x0 - 4, 0);
        const int op4 = min(x0 + 4, WW - 4);
        const int op8 = min(x0 + 8, WW - 4);

        u64 acc01 = 0ull, acc23 = 0ull;   // packed (+0,+0)

#pragma unroll
        for (int rr = 0; rr < 3; rr++) {
            const int r = rg * 3 + rr;                      // logical tap row
            const int ry = min(y + r, HH - 1);              // clamped memory row
            const float* krow = &K2s[r * 11][0] + 4 * q;    // zeros if y+r>=HH
            const float* rowb = ybase + (size_t)ry * WW;

            float4 cC[3];                 // center cache, reused in half B

            // ===== half A: d = 0..4 =====
            {
                u64 sA[5][2];
#pragma unroll
                for (int d = 0; d < 5; d++) { sA[d][0] = 0ull; sA[d][1] = 0ull; }

#pragma unroll
                for (int c = 0; c < 3; c++) {
                    const float* rc = rowb + (size_t)c * PL;
                    float w[12];
                    float4 v;
                    v = __ldg((const float4*)(rc + om8));
                    w[0] = v.x; w[1] = v.y; w[2] = v.z; w[3] = v.w;
                    v = __ldg((const float4*)(rc + om4));
                    w[4] = v.x; w[5] = v.y; w[6] = v.z; w[7] = v.w;
                    v = __ldg((const float4*)(rc + x0));
                    cC[c] = v;
                    w[8] = v.x; w[9] = v.y; w[10] = v.z; w[11] = v.w;

                    u64 P[10];
#pragma unroll
                    for (int a = 3; a <= 9; a++) P[a] = pk(w[a], w[a + 1]);

#pragma unroll
                    for (int d = 0; d < 5; d++) {
                        fma2(sA[d][0], yp01[c], P[3 + d]);
                        fma2(sA[d][1], yp23[c], P[5 + d]);
                    }
                }
#pragma unroll
                for (int d = 0; d < 5; d++) {
                    u64 k01, k23;
                    lds_v2u64(k01, k23, krow + d * 32);
                    fma2(acc01, k01, sA[d][0]);
                    fma2(acc23, k23, sA[d][1]);
                }
            }

            // ===== half B: d = 5..10, center from cache =====
            {
                u64 sB[6][2];
#pragma unroll
                for (int d = 0; d < 6; d++) { sB[d][0] = 0ull; sB[d][1] = 0ull; }

#pragma unroll
                for (int c = 0; c < 3; c++) {
                    const float* rc = rowb + (size_t)c * PL;
                    float w[12];
                    float4 v = cC[c];
                    w[0] = v.x; w[1] = v.y; w[2] = v.z; w[3] = v.w;
                    v = __ldg((const float4*)(rc + op4));
                    w[4] = v.x; w[5] = v.y; w[6] = v.z; w[7] = v.w;
                    v = __ldg((const float4*)(rc + op8));
                    w[8] = v.x; w[9] = v.y; w[10] = v.z; w[11] = v.w;

                    u64 P[8];
#pragma unroll
                    for (int a = 0; a <= 7; a++) P[a] = pk(w[a], w[a + 1]);

#pragma unroll
                    for (int d = 5; d < 11; d++) {
                        fma2(sB[d - 5][0], yp01[c], P[d - 5]);
                        fma2(sB[d - 5][1], yp23[c], P[d - 3]);
                    }
                }
#pragma unroll
                for (int d = 5; d < 11; d++) {
                    u64 k01, k23;
                    lds_v2u64(k01, k23, krow + d * 32);
                    fma2(acc01, k01, sB[d - 5][0]);
                    fma2(acc23, k23, sB[d - 5][1]);
                }
            }
        }
        float2 a01 = unpk(acc01);
        float2 a23 = unpk(acc23);
        t2 = (a01.x + a01.y) + (a23.x + a23.y);
    }

    // ---------------- Epilogue: reduce + finalize ----------------
    float v = t1 - t2;
#pragma unroll
    for (int sft = 16; sft > 0; sft >>= 1)
        v += __shfl_down_sync(0xFFFFFFFFu, v, sft);

    int lane = tid & 31, warp = tid >> 5;
    if (lane == 0) red[warp] = v;
    __syncthreads();
    if (tid == 0) {
        float bs = (red[0] + red[1]) + (red[2] + red[3]);
        int slot = ((blockIdx.y & 7) << 2) | blockIdx.x;   // 32 spread slots
        atomicAdd(&g_accs[slot], (double)bs);
        __threadfence();
        unsigned old = atomicAdd(&g_cnt, 1u);
        if (old == (unsigned)(NBLK - 1)) {
            double tot = 0.0;
#pragma unroll
            for (int i = 0; i < 32; i++) {
                tot += atomicAdd(&g_accs[i], 0.0);
                g_accs[i] = 0.0;                 // self-reset for graph replay
            }
            out[0] = (float)(tot / (double)(NIMG * HH * WW));
            g_cnt = 0u;
        }
    }
}

extern "C" void kernel_launch(void* const* d_in, const int* in_sizes, int n_in,
                              void* d_out, int out_size) {
    const float* y   = (const float*)d_in[0];
    const float* rgb = (const float*)d_in[1];
    if (n_in >= 2 && in_sizes[0] == NIMG * 3 * 256 * 256) {
        const float* t = y; y = rgb; rgb = t;
    }

    dim3 grid(4, HH, NIMG);   // 1024 blocks, single wave at 7 blocks/SM
    crf_fused<<<grid, 128>>>(y, rgb, (float*)d_out);
}